// round 3
// baseline (speedup 1.0000x reference)
#include <cuda_runtime.h>
#include <cstdint>

// Problem constants (fixed by the dataset)
#define NTAB     8
#define BUCKETS  524288          // 2^19
#define BMASK    (BUCKETS - 1)
#define EMBED    64
#define T_LEN    4096
#define HIST     128             // max window
#define POS      32              // positions per block
#define THREADS  256

__device__ __constant__ unsigned int PRIMES[8] = {
    2654435761u, 2246822519u, 3266489917u, 2028178513u,
    1220703125u, 1610612741u, 805306457u,  402653189u
};

__global__ void __launch_bounds__(THREADS)
hash_tables_kernel(const void*   __restrict__ tokens_raw,
                   const float4* __restrict__ tables,   // [8, 524288, 64] fp32 as float4
                   float4*       __restrict__ out)      // [B, T, 512] fp32 as float4
{
    __shared__ int tok_s[HIST + POS];
    __shared__ int idx_s[POS * NTAB];
    __shared__ int is32_s;

    const int*       tok32 = (const int*)tokens_raw;
    const long long* tok64 = (const long long*)tokens_raw;

    // ---- Inline dtype probe (warp 0): int64 tokens < 2^31 have zero odd
    // (high) words; genuine int32 tokens are essentially never all zero.
    if (threadIdx.x < 32) {
        unsigned any = __ballot_sync(0xFFFFFFFFu, tok32[2 * threadIdx.x + 1] != 0);
        if (threadIdx.x == 0) is32_s = (any != 0u);
    }
    __syncthreads();
    const int is32 = is32_s;

    const int blocks_per_row = T_LEN / POS;       // 128
    const int row = blockIdx.x / blocks_per_row;
    const int t0  = (blockIdx.x % blocks_per_row) * POS;

    // ---- Phase 1: stage tokens (with 128-deep history, zero-padded) ----
    for (int i = threadIdx.x; i < HIST + POS; i += THREADS) {
        const int t = t0 - HIST + i;
        int v = 0;
        if (t >= 0) {
            const size_t k = (size_t)row * T_LEN + t;
            v = is32 ? tok32[k] : (int)tok64[k];
        }
        tok_s[i] = v;
    }
    __syncthreads();

    // ---- Phase 2: rolling xor-hash, snapshot at power-of-two windows ----
    if (threadIdx.x < POS) {
        const int tp = threadIdx.x;               // position p = t0 + tp
        unsigned long long h = 0ull;
        int w = 0;
        #pragma unroll
        for (int j = 0; j < 128; ++j) {
            // contribution of token at (p - (j+1)); zero-padded tokens give 0
            const unsigned int tok = (unsigned int)tok_s[HIST + tp - 1 - j];
            h ^= (unsigned long long)tok * PRIMES[j & 7];   // IMAD.WIDE.U32
            const int offset = j + 1;
            if (offset == 1 || offset == 2 || offset == 4 || offset == 8 ||
                offset == 16 || offset == 32 || offset == 64 || offset == 128) {
                // h is nonnegative (< 2^47), so % 2^19 == low-19-bit mask
                idx_s[tp * NTAB + w] = (int)((unsigned int)h & BMASK);
                ++w;
            }
        }
    }
    __syncthreads();

    // ---- Phase 3: gather 8 x 64 floats per position, coalesced float4 copy ----
    // k enumerates float4 units: k = pos*128 + tbl*16 + f4
    const int total = POS * NTAB * 16;            // 4096 float4 per block
    const size_t out_base = ((size_t)row * T_LEN + t0) << 7;  // float4 units
    #pragma unroll 8
    for (int k = threadIdx.x; k < total; k += THREADS) {
        const int pos = k >> 7;
        const int rem = k & 127;
        const int tbl = rem >> 4;
        const int f4  = rem & 15;
        const int bucket = idx_s[pos * NTAB + tbl];
        const float4 v = __ldcs(&tables[(((size_t)tbl * BUCKETS + (size_t)bucket) << 4) + f4]);
        __stcs(&out[out_base + ((size_t)pos << 7) + rem], v);
    }
}

extern "C" void kernel_launch(void* const* d_in, const int* in_sizes, int n_in,
                              void* d_out, int out_size)
{
    const void*   tokens = d_in[0];               // int64 OR int32 (B, T) — probed
    const float4* tables = (const float4*)d_in[1];// fp32 (8, 524288, 64)
    float4*       out    = (float4*)d_out;        // fp32 (B, T, 512)

    const int rows = in_sizes[0] / T_LEN;         // B = 8
    const int grid = rows * (T_LEN / POS);        // 1024 blocks
    hash_tables_kernel<<<grid, THREADS>>>(tokens, tables, out);
}

// round 4
// speedup vs baseline: 1.4576x; 1.4576x over previous
#include <cuda_runtime.h>
#include <cstdint>

// Problem constants (fixed by the dataset)
#define NTAB     8
#define BUCKETS  524288          // 2^19
#define BMASK    (BUCKETS - 1)
#define T_LEN    4096
#define HIST     128             // deepest lag
#define POS      64              // positions per group
#define SPLIT    2               // blocks per group (redundant hash, split gather)
#define THREADS  256
#define EXT      (POS + 120)     // 184: h8 needed at positions [t0-120, t0+POS)

// Hash primes (low-32-bit arithmetic is exact for the %2^19 result)
#define P0 2654435761u
#define P1 2246822519u
#define P2 3266489917u
#define P3 2028178513u
#define P4 1220703125u
#define P5 1610612741u
#define P6 805306457u
#define P7 402653189u

__global__ void __launch_bounds__(THREADS)
hash_tables_kernel(const void*   __restrict__ tokens_raw,
                   const float4* __restrict__ tables,   // [8, 524288, 64] fp32 as float4
                   float4*       __restrict__ out)      // [B, T, 512] fp32 as float4
{
    __shared__ int      tok_s[HIST + POS];   // 192 staged tokens (zero-padded)
    __shared__ unsigned A[EXT], Bf[EXT];     // ping-pong window-hash arrays
    __shared__ int      idx_s[POS * NTAB];   // bucket ids, [pos][window]
    __shared__ int      is32_s;

    const int*       tok32 = (const int*)tokens_raw;
    const long long* tok64 = (const long long*)tokens_raw;
    const int tid = threadIdx.x;

    // ---- Inline dtype probe: int64 tokens (<2^31) have all-zero odd words ----
    if (tid < 32) {
        unsigned any = __ballot_sync(0xFFFFFFFFu, tok32[2 * tid + 1] != 0);
        if (tid == 0) is32_s = (any != 0u);
    }

    const int groups_per_row = T_LEN / POS;                 // 64
    const int group = blockIdx.x / SPLIT;
    const int part  = blockIdx.x % SPLIT;
    const int row   = group / groups_per_row;
    const int t0    = (group % groups_per_row) * POS;

    __syncthreads();
    const int is32 = is32_s;

    // ---- Phase 1: stage tokens t0-128 .. t0+POS-1 (zero-padded) ----
    for (int i = tid; i < HIST + POS; i += THREADS) {
        const int t = t0 - HIST + i;
        int v = 0;
        if (t >= 0) {
            const size_t k = (size_t)row * T_LEN + t;
            v = is32 ? tok32[k] : (int)tok64[k];
        }
        tok_s[i] = v;
    }
    __syncthreads();

    // ---- Phase 2a: h1,h2,h4,h8 chains. Position p = t0-120+i; lag-k token
    // is tok_s[i+7-k]. Snapshots for gather positions (i >= 120). ----
    if (tid < EXT) {
        const int i = tid;
        const bool snap = (i >= 120);
        const int  tp   = i - 120;
        unsigned h = (unsigned)tok_s[i + 7] * P0;                    // window 1
        if (snap) idx_s[tp * NTAB + 0] = (int)(h & BMASK);
        h ^= (unsigned)tok_s[i + 6] * P1;                            // window 2
        if (snap) idx_s[tp * NTAB + 1] = (int)(h & BMASK);
        h ^= (unsigned)tok_s[i + 5] * P2;
        h ^= (unsigned)tok_s[i + 4] * P3;                            // window 4
        if (snap) idx_s[tp * NTAB + 2] = (int)(h & BMASK);
        h ^= (unsigned)tok_s[i + 3] * P4;
        h ^= (unsigned)tok_s[i + 2] * P5;
        h ^= (unsigned)tok_s[i + 1] * P6;
        h ^= (unsigned)tok_s[i + 0] * P7;                            // window 8
        A[i] = h;
        if (snap) idx_s[tp * NTAB + 3] = (int)(h & BMASK);
    }
    __syncthreads();

    // ---- Phase 2b: log-doubling. h_{2w}(p) = h_w(p) ^ h_w(p-w). ----
    if (tid < EXT && tid >= 8) {                 // window 16
        unsigned h = A[tid] ^ A[tid - 8];
        Bf[tid] = h;
        if (tid >= 120) idx_s[(tid - 120) * NTAB + 4] = (int)(h & BMASK);
    }
    __syncthreads();
    if (tid < EXT && tid >= 24) {                // window 32
        unsigned h = Bf[tid] ^ Bf[tid - 16];
        A[tid] = h;
        if (tid >= 120) idx_s[(tid - 120) * NTAB + 5] = (int)(h & BMASK);
    }
    __syncthreads();
    if (tid < EXT && tid >= 56) {                // window 64
        unsigned h = A[tid] ^ A[tid - 32];
        Bf[tid] = h;
        if (tid >= 120) idx_s[(tid - 120) * NTAB + 6] = (int)(h & BMASK);
    }
    __syncthreads();
    if (tid >= 120 && tid < EXT) {               // window 128
        unsigned h = Bf[tid] ^ Bf[tid - 64];
        idx_s[(tid - 120) * NTAB + 7] = (int)(h & BMASK);
    }
    __syncthreads();

    // ---- Phase 3: this part gathers its half of the group's 8192 float4 ----
    // k enumerates float4 units: k = pos*128 + tbl*16 + f4
    const int part_total = POS * NTAB * 16 / SPLIT;           // 4096
    const int k0 = part * part_total;
    const size_t out_base = ((size_t)row * T_LEN + t0) << 7;  // float4 units
    #pragma unroll 8
    for (int kk = tid; kk < part_total; kk += THREADS) {
        const int k   = k0 + kk;
        const int pos = k >> 7;
        const int rem = k & 127;
        const int tbl = rem >> 4;
        const int f4  = rem & 15;
        const int bucket = idx_s[pos * NTAB + tbl];
        const float4 v = tables[(((size_t)tbl * BUCKETS + (size_t)bucket) << 4) + f4];
        out[out_base + (size_t)k] = v;
    }
}

extern "C" void kernel_launch(void* const* d_in, const int* in_sizes, int n_in,
                              void* d_out, int out_size)
{
    const void*   tokens = d_in[0];               // int64 OR int32 (B, T) — probed
    const float4* tables = (const float4*)d_in[1];// fp32 (8, 524288, 64)
    float4*       out    = (float4*)d_out;        // fp32 (B, T, 512)

    const int rows = in_sizes[0] / T_LEN;         // B = 8 (token buffer is int32-words/2 if int64;
                                                  // either way in_sizes[0] is the element count = B*T)
    const int grid = rows * (T_LEN / POS) * SPLIT; // 1024 blocks
    hash_tables_kernel<<<grid, THREADS>>>(tokens, tables, out);
}